// round 3
// baseline (speedup 1.0000x reference)
#include <cuda_runtime.h>
#include <cuda_bf16.h>

#define MM    8192
#define BSZ   16
#define HID   32
#define WIN   64
#define NNZ   131072
#define FW    512          // BSZ*HID features per node-row
#define NKCH  512          // fc1 split-K chunks
#define MPC   16           // m-rows per fc1 chunk (MM/NKCH)
#define KTOT  262144       // MM*HID

// lin1 staging geometry
#define L1_MT   16
#define L1_SMR  65                     // row stride (== 1 mod 32)
#define L1_SB   1042                   // per-b stride (== 18 mod 32)
#define L1_SMEM ((2048 + 16 * L1_SB) * 4)

// ---------------- scratch (static device globals; no runtime alloc) -------
__device__ int   g_count[MM];
__device__ int   g_rowstart[MM + 1];
__device__ int   g_cursor[MM];
__device__ unsigned long long g_ecv[NNZ];   // packed (val<<32 | col)
__device__ float g_bufA[MM * FW];           // 16 MB
__device__ float g_bufB[MM * FW];           // 16 MB
__device__ float g_stats[MM * 64];          // per-row [sum(32), sumsq(32)]
__device__ float g_stats2[64 * 64];
__device__ float g_bn[64];                  // scale[32], shift[32]
__device__ int   g_bnticket;
__device__ float g_part[NKCH * BSZ * FW];   // 16 MB fc1 split-K partials
__device__ float g_red[BSZ * 8 * FW];       // stage-1 reduced partials

// ---------------- f32x2 packed-FMA helpers (sm_103a) ----------------------
#define FMA2(d, a, b, c) asm("fma.rn.f32x2 %0, %1, %2, %3;" \
    : "=l"(d) : "l"(a), "l"(b), "l"(c))
#define PACKD(d, lo, hi) asm("mov.b64 %0, {%1, %2};" \
    : "=l"(d) : "f"(lo), "f"(hi))
#define UNPACKD(lo, hi, d) asm("mov.b64 {%0, %1}, %2;" \
    : "=f"(lo), "=f"(hi) : "l"(d))

// ================= CSR build ==============================================
__global__ void k_hist(const int* __restrict__ row) {
    int e0 = (blockIdx.x * 256 + threadIdx.x) * 4;
    int4 r = *(const int4*)(row + e0);
    atomicAdd(&g_count[r.x], 1);
    atomicAdd(&g_count[r.y], 1);
    atomicAdd(&g_count[r.z], 1);
    atomicAdd(&g_count[r.w], 1);
}

__global__ void k_scan() {  // 1 block, 1024 threads, 8 rows each
    __shared__ int sm[1024];
    int t = threadIdx.x;
    int loc[8];
    int s = 0;
#pragma unroll
    for (int i = 0; i < 8; i++) { loc[i] = g_count[t * 8 + i]; s += loc[i]; }
    sm[t] = s;
    __syncthreads();
    for (int off = 1; off < 1024; off <<= 1) {
        int v = (t >= off) ? sm[t - off] : 0;
        __syncthreads();
        sm[t] += v;
        __syncthreads();
    }
    int run = (t == 0) ? 0 : sm[t - 1];
#pragma unroll
    for (int i = 0; i < 8; i++) {
        g_rowstart[t * 8 + i] = run;
        g_cursor[t * 8 + i] = run;
        run += loc[i];
    }
    if (t == 1023) g_rowstart[MM] = run;
}

__global__ void k_scatter(const int* __restrict__ row, const int* __restrict__ col,
                          const float* __restrict__ val) {
    int e0 = (blockIdx.x * 256 + threadIdx.x) * 4;
    int4 r = *(const int4*)(row + e0);
    int4 c = *(const int4*)(col + e0);
    float4 v = *(const float4*)(val + e0);
    int p0 = atomicAdd(&g_cursor[r.x], 1);
    g_ecv[p0] = ((unsigned long long)__float_as_uint(v.x) << 32) | (unsigned)c.x;
    int p1 = atomicAdd(&g_cursor[r.y], 1);
    g_ecv[p1] = ((unsigned long long)__float_as_uint(v.y) << 32) | (unsigned)c.y;
    int p2 = atomicAdd(&g_cursor[r.z], 1);
    g_ecv[p2] = ((unsigned long long)__float_as_uint(v.z) << 32) | (unsigned)c.z;
    int p3 = atomicAdd(&g_cursor[r.w], 1);
    g_ecv[p3] = ((unsigned long long)__float_as_uint(v.w) << 32) | (unsigned)c.w;
}

// ================= layer-1 linear: bufA[(m,b),:] = inputs[b,m,:] @ W1 =====
// Staged + f32x2 packed over b-pairs. Block: 128 thr, 16 m-rows, all 16 b.
__global__ void __launch_bounds__(128) k_lin1(const float* __restrict__ x,
                                              const float* __restrict__ W) {
    extern __shared__ float dsm[];
    float* w  = dsm;                 // 2048 floats
    float* xs = dsm + 2048;          // 16 * L1_SB floats, padded
    int t = threadIdx.x;
    int m0 = blockIdx.x * L1_MT;
    for (int i = t; i < WIN * HID; i += 128) w[i] = W[i];
#pragma unroll
    for (int b = 0; b < BSZ; b++) {
        const float* src = x + ((size_t)b * MM + m0) * WIN;
        float* dst = xs + b * L1_SB;
        for (int i = t; i < L1_MT * WIN; i += 128)
            dst[(i >> 6) * L1_SMR + (i & 63)] = src[i];
    }
    __syncthreads();
    int b0 = (t & 7) * 2;
    int mi = t >> 3;
    const float* xr0 = xs + b0 * L1_SB + mi * L1_SMR;
    const float* xr1 = xr0 + L1_SB;
    unsigned long long acc0[16], acc1[16];
#pragma unroll
    for (int i = 0; i < 16; i++) { acc0[i] = 0ULL; acc1[i] = 0ULL; }
#pragma unroll 8
    for (int k = 0; k < WIN; k++) {
        float e0 = xr0[k], e1 = xr1[k];
        unsigned long long d0, d1;
        PACKD(d0, e0, e0); PACKD(d1, e1, e1);
        const ulonglong2* wr = (const ulonglong2*)(w + k * HID);
#pragma unroll
        for (int q = 0; q < 8; q++) {
            ulonglong2 wp = wr[q];
            FMA2(acc0[2 * q + 0], d0, wp.x, acc0[2 * q + 0]);
            FMA2(acc0[2 * q + 1], d0, wp.y, acc0[2 * q + 1]);
            FMA2(acc1[2 * q + 0], d1, wp.x, acc1[2 * q + 0]);
            FMA2(acc1[2 * q + 1], d1, wp.y, acc1[2 * q + 1]);
        }
    }
    int m = m0 + mi;
    ulonglong2* o0 = (ulonglong2*)(g_bufA + ((size_t)m * BSZ + b0) * HID);
    ulonglong2* o1 = (ulonglong2*)(g_bufA + ((size_t)m * BSZ + b0 + 1) * HID);
#pragma unroll
    for (int q = 0; q < 8; q++) {
        ulonglong2 v0; v0.x = acc0[2 * q]; v0.y = acc0[2 * q + 1];
        ulonglong2 v1; v1.x = acc1[2 * q]; v1.y = acc1[2 * q + 1];
        o0[q] = v0;
        o1[q] = v1;
    }
}

// ================= SpMM: y[r,:] = sum_e val*x[col,:] + bias; + BN partials =
__global__ void k_spmm(const float* __restrict__ x, const float* __restrict__ bias,
                       float* __restrict__ y) {
    int r = blockIdx.x;
    int t = threadIdx.x;                 // 128 threads, 4 features each
    __shared__ unsigned long long ecv[128];
    __shared__ float4 ssum[128];
    __shared__ float4 ssq[128];
    int s = g_rowstart[r], e = g_rowstart[r + 1];
    int t4 = t * 4;
    float4 a0 = {0,0,0,0}, a1 = {0,0,0,0}, a2 = {0,0,0,0}, a3 = {0,0,0,0};
    for (int base = s; base < e; base += 128) {
        int n = min(128, e - base);
        __syncthreads();
        if (t < n) ecv[t] = g_ecv[base + t];
        __syncthreads();
        int i = 0;
        for (; i + 4 <= n; i += 4) {
            unsigned long long u0 = ecv[i], u1 = ecv[i+1], u2 = ecv[i+2], u3 = ecv[i+3];
            float v0 = __uint_as_float((unsigned)(u0 >> 32));
            float v1 = __uint_as_float((unsigned)(u1 >> 32));
            float v2 = __uint_as_float((unsigned)(u2 >> 32));
            float v3 = __uint_as_float((unsigned)(u3 >> 32));
            float4 x0 = *(const float4*)(x + (size_t)(unsigned)(u0 & 0xffffffffu) * FW + t4);
            float4 x1 = *(const float4*)(x + (size_t)(unsigned)(u1 & 0xffffffffu) * FW + t4);
            float4 x2 = *(const float4*)(x + (size_t)(unsigned)(u2 & 0xffffffffu) * FW + t4);
            float4 x3 = *(const float4*)(x + (size_t)(unsigned)(u3 & 0xffffffffu) * FW + t4);
            a0.x += v0 * x0.x; a0.y += v0 * x0.y; a0.z += v0 * x0.z; a0.w += v0 * x0.w;
            a1.x += v1 * x1.x; a1.y += v1 * x1.y; a1.z += v1 * x1.z; a1.w += v1 * x1.w;
            a2.x += v2 * x2.x; a2.y += v2 * x2.y; a2.z += v2 * x2.z; a2.w += v2 * x2.w;
            a3.x += v3 * x3.x; a3.y += v3 * x3.y; a3.z += v3 * x3.z; a3.w += v3 * x3.w;
        }
        for (; i < n; i++) {
            unsigned long long u = ecv[i];
            float v = __uint_as_float((unsigned)(u >> 32));
            float4 xv = *(const float4*)(x + (size_t)(unsigned)(u & 0xffffffffu) * FW + t4);
            a0.x += v * xv.x; a0.y += v * xv.y; a0.z += v * xv.z; a0.w += v * xv.w;
        }
    }
    float4 acc;
    acc.x = (a0.x + a1.x) + (a2.x + a3.x);
    acc.y = (a0.y + a1.y) + (a2.y + a3.y);
    acc.z = (a0.z + a1.z) + (a2.z + a3.z);
    acc.w = (a0.w + a1.w) + (a2.w + a3.w);
    int c0 = (t & 7) * 4;                // channel base (feature = b*32+c)
    float4 bv = *(const float4*)(bias + c0);
    acc.x += bv.x; acc.y += bv.y; acc.z += bv.z; acc.w += bv.w;
    *(float4*)(y + (size_t)r * FW + t4) = acc;
    ssum[t] = acc;
    float4 sq = {acc.x * acc.x, acc.y * acc.y, acc.z * acc.z, acc.w * acc.w};
    ssq[t] = sq;
    __syncthreads();
    if (t < 8) {                         // deterministic reduce over 16 b
        float4 a = {0, 0, 0, 0}, q = {0, 0, 0, 0};
        for (int k = 0; k < 16; k++) {
            float4 u = ssum[k * 8 + t], v = ssq[k * 8 + t];
            a.x += u.x; a.y += u.y; a.z += u.z; a.w += u.w;
            q.x += v.x; q.y += v.y; q.z += v.z; q.w += v.w;
        }
        *(float4*)(g_stats + (size_t)r * 64 + t * 4) = a;
        *(float4*)(g_stats + (size_t)r * 64 + 32 + t * 4) = q;
    }
}

// ================= fused BN reduction (ticket / last-block) ===============
__global__ void k_bn(const float* __restrict__ g, const float* __restrict__ be) {
    int bx = blockIdx.x, t = threadIdx.x;      // grid 64, 256 threads
    int col = t & 63, seg = t >> 6;            // 4 segments x 32 rows
    float s = 0.f;
    int r0 = bx * 128 + seg * 32;
    for (int i = 0; i < 32; i++) s += g_stats[(size_t)(r0 + i) * 64 + col];
    __shared__ float sm[256];
    sm[t] = s;
    __syncthreads();
    if (seg == 0)
        g_stats2[bx * 64 + col] = sm[col] + sm[64 + col] + sm[128 + col] + sm[192 + col];
    __threadfence();
    __shared__ int lastFlag;
    if (t == 0) lastFlag = (atomicAdd(&g_bnticket, 1) == 63);
    __syncthreads();
    if (lastFlag) {
        if (t < 64) {
            float ss = 0.f;
            for (int i = 0; i < 64; i++) ss += g_stats2[i * 64 + t];
            sm[t] = ss;
        }
        __syncthreads();
        if (t < 32) {
            const float inv_n = 1.f / (float)(BSZ * MM);
            float mean = sm[t] * inv_n;
            float var = sm[32 + t] * inv_n - mean * mean;
            float sc = g[t] * rsqrtf(var + 1e-5f);
            g_bn[t] = sc;
            g_bn[32 + t] = be[t] - mean * sc;
        }
        if (t == 0) g_bnticket = 0;   // reset for next use / replay
    }
}

// ================= layer-2 linear, staged + f32x2, fused BN+ReLU ==========
// Block: 128 threads, each owns a contiguous row-pair (rows 2p, 2p+1).
__global__ void __launch_bounds__(128) k_lin2(const float* __restrict__ y,
                                              const float* __restrict__ W,
                                              float* __restrict__ out) {
    __shared__ float w[HID * HID];       // 4 KB
    __shared__ float xs[128 * 65];       // 33.3 KB, pair stride 65 (==1 mod 32)
    __shared__ float sc[32], sh[32];
    int t = threadIdx.x;
    for (int i = t; i < HID * HID; i += 128) w[i] = W[i];
    if (t < 32) { sc[t] = g_bn[t]; sh[t] = g_bn[32 + t]; }
    int r0 = blockIdx.x * 256;           // 256 rows = 128 pairs per block
    const float* src = y + (size_t)r0 * HID;
    for (int i = t; i < 256 * HID; i += 128)
        xs[(i >> 6) * 65 + (i & 63)] = src[i];
    __syncthreads();
    const float* xr0 = xs + t * 65;      // row 2t (32 floats), then row 2t+1
    const float* xr1 = xr0 + 32;
    unsigned long long acc0[16], acc1[16];
#pragma unroll
    for (int i = 0; i < 16; i++) { acc0[i] = 0ULL; acc1[i] = 0ULL; }
#pragma unroll 8
    for (int c = 0; c < HID; c++) {
        float e0 = fmaxf(sc[c] * xr0[c] + sh[c], 0.f);
        float e1 = fmaxf(sc[c] * xr1[c] + sh[c], 0.f);
        unsigned long long d0, d1;
        PACKD(d0, e0, e0); PACKD(d1, e1, e1);
        const ulonglong2* wr = (const ulonglong2*)(w + c * HID);
#pragma unroll
        for (int q = 0; q < 8; q++) {
            ulonglong2 wp = wr[q];
            FMA2(acc0[2 * q + 0], d0, wp.x, acc0[2 * q + 0]);
            FMA2(acc0[2 * q + 1], d0, wp.y, acc0[2 * q + 1]);
            FMA2(acc1[2 * q + 0], d1, wp.x, acc1[2 * q + 0]);
            FMA2(acc1[2 * q + 1], d1, wp.y, acc1[2 * q + 1]);
        }
    }
    ulonglong2* o = (ulonglong2*)(out + (size_t)(r0 + 2 * t) * HID);
#pragma unroll
    for (int q = 0; q < 8; q++) {
        ulonglong2 v; v.x = acc0[2 * q]; v.y = acc0[2 * q + 1];
        o[q] = v;
    }
#pragma unroll
    for (int q = 0; q < 8; q++) {
        ulonglong2 v; v.x = acc1[2 * q]; v.y = acc1[2 * q + 1];
        o[8 + q] = v;
    }
}

// ================= fc1 split-K GEMM with f32x2 and fused BN+ReLU ==========
__global__ void __launch_bounds__(128) k_fc1(const float* __restrict__ w,
                                             const float* __restrict__ y2) {
    int ck = blockIdx.x;                  // K-chunk: m in [ck*16, ck*16+16)
    int t = threadIdx.x;                  // thread owns 4 j-cols, all 16 b
    __shared__ __align__(16) float xs[MPC * FW];   // 32 KB: xs[(mi*32+c)*16 + b]
    __shared__ float sc[32], sh[32];
    if (t < 32) { sc[t] = g_bn[t]; sh[t] = g_bn[32 + t]; }
    __syncthreads();
    // stage all MPC rows once: BN + ReLU + transpose
    {
        int b = t >> 3;
        int c0 = (t & 7) * 4;
        float s0 = sc[c0 + 0], s1 = sc[c0 + 1], s2 = sc[c0 + 2], s3 = sc[c0 + 3];
        float h0 = sh[c0 + 0], h1 = sh[c0 + 1], h2 = sh[c0 + 2], h3 = sh[c0 + 3];
#pragma unroll
        for (int mi = 0; mi < MPC; mi++) {
            float4 v = ((const float4*)(y2 + (size_t)(ck * MPC + mi) * FW))[t];
            float* xr = xs + mi * FW;
            xr[(c0 + 0) * 16 + b] = fmaxf(s0 * v.x + h0, 0.f);
            xr[(c0 + 1) * 16 + b] = fmaxf(s1 * v.y + h1, 0.f);
            xr[(c0 + 2) * 16 + b] = fmaxf(s2 * v.z + h2, 0.f);
            xr[(c0 + 3) * 16 + b] = fmaxf(s3 * v.w + h3, 0.f);
        }
    }
    __syncthreads();
    unsigned long long acc[32];           // [b-pair(8)][j(4)]
#pragma unroll
    for (int i = 0; i < 32; i++) acc[i] = 0ULL;
    int j0 = t * 4;
    const float* wp = w + (size_t)ck * MPC * HID * FW + j0;
#pragma unroll 4
    for (int kc = 0; kc < MPC * HID; kc++) {     // kc = mi*32 + c, streams w
        float4 wv = *(const float4*)(wp + (size_t)kc * FW);
        unsigned long long w2x, w2y, w2z, w2w;
        PACKD(w2x, wv.x, wv.x); PACKD(w2y, wv.y, wv.y);
        PACKD(w2z, wv.z, wv.z); PACKD(w2w, wv.w, wv.w);
        const ulonglong2* xp = (const ulonglong2*)(xs + kc * 16);
#pragma unroll
        for (int q = 0; q < 4; q++) {
            ulonglong2 xv = xp[q];      // b-pairs (2q, 2q+1)
            FMA2(acc[(2 * q + 0) * 4 + 0], xv.x, w2x, acc[(2 * q + 0) * 4 + 0]);
            FMA2(acc[(2 * q + 0) * 4 + 1], xv.x, w2y, acc[(2 * q + 0) * 4 + 1]);
            FMA2(acc[(2 * q + 0) * 4 + 2], xv.x, w2z, acc[(2 * q + 0) * 4 + 2]);
            FMA2(acc[(2 * q + 0) * 4 + 3], xv.x, w2w, acc[(2 * q + 0) * 4 + 3]);
            FMA2(acc[(2 * q + 1) * 4 + 0], xv.y, w2x, acc[(2 * q + 1) * 4 + 0]);
            FMA2(acc[(2 * q + 1) * 4 + 1], xv.y, w2y, acc[(2 * q + 1) * 4 + 1]);
            FMA2(acc[(2 * q + 1) * 4 + 2], xv.y, w2z, acc[(2 * q + 1) * 4 + 2]);
            FMA2(acc[(2 * q + 1) * 4 + 3], xv.y, w2w, acc[(2 * q + 1) * 4 + 3]);
        }
    }
    float* pbase = g_part + (size_t)ck * BSZ * FW;
#pragma unroll
    for (int b2 = 0; b2 < 8; b2++) {
        float lo0, hi0, lo1, hi1, lo2, hi2, lo3, hi3;
        UNPACKD(lo0, hi0, acc[b2 * 4 + 0]);
        UNPACKD(lo1, hi1, acc[b2 * 4 + 1]);
        UNPACKD(lo2, hi2, acc[b2 * 4 + 2]);
        UNPACKD(lo3, hi3, acc[b2 * 4 + 3]);
        float4 ev = {lo0, lo1, lo2, lo3};
        float4 ov = {hi0, hi1, hi2, hi3};
        *(float4*)(pbase + (size_t)(2 * b2 + 0) * FW + j0) = ev;
        *(float4*)(pbase + (size_t)(2 * b2 + 1) * FW + j0) = ov;
    }
}

// ================= reduce partials (stage 1, coalesced float4) ============
__global__ void k_red1() {
    int b = blockIdx.x >> 3;             // 0..15
    int grp = blockIdx.x & 7;            // 0..7, each covers 64 chunks
    int t = threadIdx.x;                 // 128 threads, j-quad each
    const float* p = g_part + (size_t)(grp * 64) * BSZ * FW + (size_t)b * FW + t * 4;
    float4 s = {0, 0, 0, 0};
#pragma unroll 8
    for (int k = 0; k < 64; k++) {
        float4 v = *(const float4*)(p + (size_t)k * BSZ * FW);
        s.x += v.x; s.y += v.y; s.z += v.z; s.w += v.w;
    }
    *(float4*)(g_red + (size_t)(b * 8 + grp) * FW + t * 4) = s;
}

// ================= final: reduce + extras + bias + relu + fc2 =============
__global__ void k_red2(const float* __restrict__ w, const float* __restrict__ fc1b,
                       const float* __restrict__ ex, const float* __restrict__ fc2w,
                       const float* __restrict__ fc2b, float* __restrict__ out) {
    int b = blockIdx.x;                  // 16 blocks
    int j = threadIdx.x;                 // 512 threads
    float acc = fc1b[j];
#pragma unroll
    for (int g = 0; g < 8; g++) acc += g_red[(size_t)(b * 8 + g) * FW + j];
#pragma unroll
    for (int e2 = 0; e2 < 32; e2++)
        acc += ex[b * 32 + e2] * w[((size_t)KTOT + e2) * FW + j];
    float h = fmaxf(acc, 0.f);
    __shared__ float r0[512], r1[512];
    r0[j] = h * fc2w[j * 2 + 0];
    r1[j] = h * fc2w[j * 2 + 1];
    __syncthreads();
    for (int s = 256; s > 0; s >>= 1) {
        if (j < s) { r0[j] += r0[j + s]; r1[j] += r1[j + s]; }
        __syncthreads();
    }
    if (j == 0) {
        out[b * 2 + 0] = r0[0] + fc2b[0];
        out[b * 2 + 1] = r1[0] + fc2b[1];
    }
}

// ================= launch ==================================================
extern "C" void kernel_launch(void* const* d_in, const int* in_sizes, int n_in,
                              void* d_out, int out_size) {
    const float* inputs  = (const float*)d_in[0];
    const float* ex      = (const float*)d_in[1];
    const int*   erow    = (const int*)  d_in[2];
    const int*   ecol    = (const int*)  d_in[3];
    const float* eval    = (const float*)d_in[4];
    const float* W1      = (const float*)d_in[5];
    const float* b1      = (const float*)d_in[6];
    const float* g1      = (const float*)d_in[7];
    const float* be1     = (const float*)d_in[8];
    const float* W2      = (const float*)d_in[9];
    const float* b2      = (const float*)d_in[10];
    const float* g2      = (const float*)d_in[11];
    const float* be2     = (const float*)d_in[12];
    const float* fc1w    = (const float*)d_in[13];
    const float* fc1b    = (const float*)d_in[14];
    const float* fc2w    = (const float*)d_in[15];
    const float* fc2b    = (const float*)d_in[16];
    float* out = (float*)d_out;

    float* bufA; cudaGetSymbolAddress((void**)&bufA, g_bufA);
    float* bufB; cudaGetSymbolAddress((void**)&bufB, g_bufB);
    int* cnt;    cudaGetSymbolAddress((void**)&cnt,  g_count);

    cudaFuncSetAttribute(k_lin1, cudaFuncAttributeMaxDynamicSharedMemorySize, L1_SMEM);

    cudaMemsetAsync(cnt, 0, MM * sizeof(int));
    k_hist<<<NNZ / 1024, 256>>>(erow);
    k_scan<<<1, 1024>>>();
    k_scatter<<<NNZ / 1024, 256>>>(erow, ecol, eval);

    k_lin1<<<MM / L1_MT, 128, L1_SMEM>>>(inputs, W1);       // bufA = X@W1 (m,b,c)
    k_spmm<<<MM, 128>>>(bufA, b1, bufB);                    // bufB = L@bufA + b1, stats
    k_bn<<<64, 256>>>(g1, be1);
    k_lin2<<<(BSZ * MM) / 256, 128>>>(bufB, W2, bufA);      // bufA = bnrelu(bufB)@W2
    k_spmm<<<MM, 128>>>(bufA, b2, bufB);                    // bufB = L@bufA + b2, stats
    k_bn<<<64, 256>>>(g2, be2);

    k_fc1<<<NKCH, 128>>>(fc1w, bufB);                       // split-K partials
    k_red1<<<BSZ * 8, 128>>>();                             // coalesced partial reduce
    k_red2<<<BSZ, 512>>>(fc1w, fc1b, ex, fc2w, fc2b, out);  // finish + fc2
}

// round 4
// speedup vs baseline: 1.2757x; 1.2757x over previous
#include <cuda_runtime.h>
#include <cuda_bf16.h>

#define MM    8192
#define BSZ   16
#define HID   32
#define WIN   64
#define NNZ   131072
#define FW    512          // BSZ*HID features per node-row
#define NKCH  512          // fc1 split-K chunks
#define MPC   16           // m-rows per fc1 chunk (MM/NKCH)
#define KTOT  262144       // MM*HID

// ---------------- scratch (static device globals; no runtime alloc) -------
__device__ int   g_count[MM];
__device__ int   g_rowstart[MM + 1];
__device__ int   g_cursor[MM];
__device__ unsigned long long g_ecv[NNZ];   // packed (val<<32 | col)
__device__ float g_bufA[MM * FW];           // 16 MB
__device__ float g_bufB[MM * FW];           // 16 MB
__device__ float g_stats[MM * 64];          // per-row [sum(32), sumsq(32)]
__device__ float g_stats2[64 * 64];
__device__ float g_bn[64];                  // scale[32], shift[32]
__device__ int   g_bnticket;
__device__ float g_part[NKCH * BSZ * FW];   // 16 MB fc1 split-K partials
__device__ float g_red[BSZ * 8 * FW];       // stage-1 reduced partials

// ---------------- f32x2 packed-FMA helpers (sm_103a) ----------------------
#define FMA2(d, a, b, c) asm("fma.rn.f32x2 %0, %1, %2, %3;" \
    : "=l"(d) : "l"(a), "l"(b), "l"(c))
#define PACKD(d, lo, hi) asm("mov.b64 %0, {%1, %2};" \
    : "=l"(d) : "f"(lo), "f"(hi))
#define UNPACKD(lo, hi, d) asm("mov.b64 {%0, %1}, %2;" \
    : "=f"(lo), "=f"(hi) : "l"(d))

// ================= CSR build ==============================================
__global__ void k_hist(const int* __restrict__ row) {
    int e0 = (blockIdx.x * 256 + threadIdx.x) * 4;
    int4 r = *(const int4*)(row + e0);
    atomicAdd(&g_count[r.x], 1);
    atomicAdd(&g_count[r.y], 1);
    atomicAdd(&g_count[r.z], 1);
    atomicAdd(&g_count[r.w], 1);
}

__global__ void k_scan() {  // 1 block, 1024 threads, 8 rows each
    __shared__ int sm[1024];
    int t = threadIdx.x;
    int loc[8];
    int s = 0;
#pragma unroll
    for (int i = 0; i < 8; i++) { loc[i] = g_count[t * 8 + i]; s += loc[i]; }
    sm[t] = s;
    __syncthreads();
    for (int off = 1; off < 1024; off <<= 1) {
        int v = (t >= off) ? sm[t - off] : 0;
        __syncthreads();
        sm[t] += v;
        __syncthreads();
    }
    int run = (t == 0) ? 0 : sm[t - 1];
#pragma unroll
    for (int i = 0; i < 8; i++) {
        g_rowstart[t * 8 + i] = run;
        g_cursor[t * 8 + i] = run;
        run += loc[i];
    }
    if (t == 1023) g_rowstart[MM] = run;
}

__global__ void k_scatter(const int* __restrict__ row, const int* __restrict__ col,
                          const float* __restrict__ val) {
    int e0 = (blockIdx.x * 256 + threadIdx.x) * 4;
    int4 r = *(const int4*)(row + e0);
    int4 c = *(const int4*)(col + e0);
    float4 v = *(const float4*)(val + e0);
    int p0 = atomicAdd(&g_cursor[r.x], 1);
    g_ecv[p0] = ((unsigned long long)__float_as_uint(v.x) << 32) | (unsigned)c.x;
    int p1 = atomicAdd(&g_cursor[r.y], 1);
    g_ecv[p1] = ((unsigned long long)__float_as_uint(v.y) << 32) | (unsigned)c.y;
    int p2 = atomicAdd(&g_cursor[r.z], 1);
    g_ecv[p2] = ((unsigned long long)__float_as_uint(v.z) << 32) | (unsigned)c.z;
    int p3 = atomicAdd(&g_cursor[r.w], 1);
    g_ecv[p3] = ((unsigned long long)__float_as_uint(v.w) << 32) | (unsigned)c.w;
}

// ================= layer-1 linear: bufA[(m,b),:] = inputs[b,m,:] @ W1 =====
// 256 thr/block; tile = 8 m x 16 b = 128 rows staged in smem; half-row/thread.
__global__ void __launch_bounds__(256) k_lin1(const float* __restrict__ x,
                                              const float* __restrict__ W) {
    __shared__ __align__(16) float w[WIN * HID];   // 8 KB
    __shared__ __align__(16) float xs[128 * 65];   // 33.3 KB, row r = mm*16+b
    int t = threadIdx.x;
    int m0 = blockIdx.x * 8;
    for (int i = t; i < WIN * HID; i += 256) w[i] = W[i];
#pragma unroll
    for (int p = 0; p < 32; p++) {                 // 8192 floats staged
        int i = t + p * 256;
        int b = i >> 9, mm = (i >> 6) & 7, f = i & 63;
        xs[(mm * 16 + b) * 65 + f] = x[((size_t)b * MM + m0 + mm) * WIN + f];
    }
    __syncthreads();
    int r = t >> 1;                  // in-tile row 0..127 (mm*16+b)
    int h = t & 1;                   // channel half: c in [h*16, h*16+16)
    const float* xr = xs + r * 65;
    const float* wh = w + h * 16;
    unsigned long long acc[8];
#pragma unroll
    for (int i = 0; i < 8; i++) acc[i] = 0ULL;
#pragma unroll 8
    for (int k = 0; k < WIN; k++) {
        float xv = xr[k];
        unsigned long long xd;
        PACKD(xd, xv, xv);
        const ulonglong2* wr = (const ulonglong2*)(wh + k * HID);
#pragma unroll
        for (int q = 0; q < 4; q++) {
            ulonglong2 wp = wr[q];
            FMA2(acc[2 * q + 0], xd, wp.x, acc[2 * q + 0]);
            FMA2(acc[2 * q + 1], xd, wp.y, acc[2 * q + 1]);
        }
    }
    int mm = r >> 4, b = r & 15;
    float* o = g_bufA + ((size_t)(m0 + mm) * BSZ + b) * HID + h * 16;
#pragma unroll
    for (int q = 0; q < 4; q++) {
        float lo0, hi0, lo1, hi1;
        UNPACKD(lo0, hi0, acc[2 * q + 0]);
        UNPACKD(lo1, hi1, acc[2 * q + 1]);
        float4 v = {lo0, hi0, lo1, hi1};
        *(float4*)(o + q * 4) = v;
    }
}

// ================= SpMM: y[r,:] = sum_e val*x[col,:] + bias; + BN partials =
__global__ void k_spmm(const float* __restrict__ x, const float* __restrict__ bias,
                       float* __restrict__ y) {
    int r = blockIdx.x;
    int t = threadIdx.x;                 // 128 threads, 4 features each
    __shared__ unsigned long long ecv[128];
    __shared__ float4 ssum[128];
    __shared__ float4 ssq[128];
    int s = g_rowstart[r], e = g_rowstart[r + 1];
    int t4 = t * 4;
    float4 a0 = {0,0,0,0}, a1 = {0,0,0,0}, a2 = {0,0,0,0}, a3 = {0,0,0,0};
    for (int base = s; base < e; base += 128) {
        int n = min(128, e - base);
        __syncthreads();
        if (t < n) ecv[t] = g_ecv[base + t];
        __syncthreads();
        int i = 0;
        for (; i + 4 <= n; i += 4) {
            unsigned long long u0 = ecv[i], u1 = ecv[i+1], u2 = ecv[i+2], u3 = ecv[i+3];
            float v0 = __uint_as_float((unsigned)(u0 >> 32));
            float v1 = __uint_as_float((unsigned)(u1 >> 32));
            float v2 = __uint_as_float((unsigned)(u2 >> 32));
            float v3 = __uint_as_float((unsigned)(u3 >> 32));
            float4 x0 = *(const float4*)(x + (size_t)(unsigned)(u0 & 0xffffffffu) * FW + t4);
            float4 x1 = *(const float4*)(x + (size_t)(unsigned)(u1 & 0xffffffffu) * FW + t4);
            float4 x2 = *(const float4*)(x + (size_t)(unsigned)(u2 & 0xffffffffu) * FW + t4);
            float4 x3 = *(const float4*)(x + (size_t)(unsigned)(u3 & 0xffffffffu) * FW + t4);
            a0.x += v0 * x0.x; a0.y += v0 * x0.y; a0.z += v0 * x0.z; a0.w += v0 * x0.w;
            a1.x += v1 * x1.x; a1.y += v1 * x1.y; a1.z += v1 * x1.z; a1.w += v1 * x1.w;
            a2.x += v2 * x2.x; a2.y += v2 * x2.y; a2.z += v2 * x2.z; a2.w += v2 * x2.w;
            a3.x += v3 * x3.x; a3.y += v3 * x3.y; a3.z += v3 * x3.z; a3.w += v3 * x3.w;
        }
        for (; i < n; i++) {
            unsigned long long u = ecv[i];
            float v = __uint_as_float((unsigned)(u >> 32));
            float4 xv = *(const float4*)(x + (size_t)(unsigned)(u & 0xffffffffu) * FW + t4);
            a0.x += v * xv.x; a0.y += v * xv.y; a0.z += v * xv.z; a0.w += v * xv.w;
        }
    }
    float4 acc;
    acc.x = (a0.x + a1.x) + (a2.x + a3.x);
    acc.y = (a0.y + a1.y) + (a2.y + a3.y);
    acc.z = (a0.z + a1.z) + (a2.z + a3.z);
    acc.w = (a0.w + a1.w) + (a2.w + a3.w);
    int c0 = (t & 7) * 4;                // channel base (feature = b*32+c)
    float4 bv = *(const float4*)(bias + c0);
    acc.x += bv.x; acc.y += bv.y; acc.z += bv.z; acc.w += bv.w;
    *(float4*)(y + (size_t)r * FW + t4) = acc;
    ssum[t] = acc;
    float4 sq = {acc.x * acc.x, acc.y * acc.y, acc.z * acc.z, acc.w * acc.w};
    ssq[t] = sq;
    __syncthreads();
    if (t < 8) {                         // deterministic reduce over 16 b
        float4 a = {0, 0, 0, 0}, q = {0, 0, 0, 0};
        for (int k = 0; k < 16; k++) {
            float4 u = ssum[k * 8 + t], v = ssq[k * 8 + t];
            a.x += u.x; a.y += u.y; a.z += u.z; a.w += u.w;
            q.x += v.x; q.y += v.y; q.z += v.z; q.w += v.w;
        }
        *(float4*)(g_stats + (size_t)r * 64 + t * 4) = a;
        *(float4*)(g_stats + (size_t)r * 64 + 32 + t * 4) = q;
    }
}

// ================= fused BN reduction (ticket / last-block) ===============
__global__ void k_bn(const float* __restrict__ g, const float* __restrict__ be) {
    int bx = blockIdx.x, t = threadIdx.x;      // grid 64, 256 threads
    int col = t & 63, seg = t >> 6;            // 4 segments x 32 rows
    float s = 0.f;
    int r0 = bx * 128 + seg * 32;
    for (int i = 0; i < 32; i++) s += g_stats[(size_t)(r0 + i) * 64 + col];
    __shared__ float sm[256];
    sm[t] = s;
    __syncthreads();
    if (seg == 0)
        g_stats2[bx * 64 + col] = sm[col] + sm[64 + col] + sm[128 + col] + sm[192 + col];
    __threadfence();
    __shared__ int lastFlag;
    if (t == 0) lastFlag = (atomicAdd(&g_bnticket, 1) == 63);
    __syncthreads();
    if (lastFlag) {
        if (t < 64) {
            float ss = 0.f;
            for (int i = 0; i < 64; i++) ss += g_stats2[i * 64 + t];
            sm[t] = ss;
        }
        __syncthreads();
        if (t < 32) {
            const float inv_n = 1.f / (float)(BSZ * MM);
            float mean = sm[t] * inv_n;
            float var = sm[32 + t] * inv_n - mean * mean;
            float sc = g[t] * rsqrtf(var + 1e-5f);
            g_bn[t] = sc;
            g_bn[32 + t] = be[t] - mean * sc;
        }
        if (t == 0) g_bnticket = 0;   // reset for next use / replay
    }
}

// ================= layer-2 linear, staged + f32x2, fused BN+ReLU ==========
// 256 thr/block; 128 contiguous rows staged with BN+ReLU; half-row/thread.
__global__ void __launch_bounds__(256) k_lin2(const float* __restrict__ y,
                                              const float* __restrict__ W,
                                              float* __restrict__ out) {
    __shared__ __align__(16) float w[HID * HID];   // 4 KB
    __shared__ __align__(16) float xs[128 * 33];   // 16.9 KB
    __shared__ float sc[32], sh[32];
    int t = threadIdx.x;
    for (int i = t; i < HID * HID; i += 256) w[i] = W[i];
    if (t < 32) { sc[t] = g_bn[t]; sh[t] = g_bn[32 + t]; }
    __syncthreads();
    int r0 = blockIdx.x * 128;
    float bs = sc[t & 31], bh = sh[t & 31];        // channel = i & 31 = t & 31
    const float* src = y + (size_t)r0 * HID;
#pragma unroll
    for (int p = 0; p < 16; p++) {                 // 4096 floats staged + BN/ReLU
        int i = t + p * 256;
        xs[(i >> 5) * 33 + (t & 31)] = fmaxf(bs * src[i] + bh, 0.f);
    }
    __syncthreads();
    int r = t >> 1;
    int h = t & 1;
    const float* xr = xs + r * 33;
    const float* wh = w + h * 16;
    unsigned long long acc[8];
#pragma unroll
    for (int i = 0; i < 8; i++) acc[i] = 0ULL;
#pragma unroll 8
    for (int k = 0; k < HID; k++) {
        float xv = xr[k];
        unsigned long long xd;
        PACKD(xd, xv, xv);
        const ulonglong2* wr = (const ulonglong2*)(wh + k * HID);
#pragma unroll
        for (int q = 0; q < 4; q++) {
            ulonglong2 wp = wr[q];
            FMA2(acc[2 * q + 0], xd, wp.x, acc[2 * q + 0]);
            FMA2(acc[2 * q + 1], xd, wp.y, acc[2 * q + 1]);
        }
    }
    float* o = out + (size_t)(r0 + r) * HID + h * 16;
#pragma unroll
    for (int q = 0; q < 4; q++) {
        float lo0, hi0, lo1, hi1;
        UNPACKD(lo0, hi0, acc[2 * q + 0]);
        UNPACKD(lo1, hi1, acc[2 * q + 1]);
        float4 v = {lo0, hi0, lo1, hi1};
        *(float4*)(o + q * 4) = v;
    }
}

// ================= fc1 split-K GEMM: 256 thr, prefetch, f32x2 =============
__global__ void __launch_bounds__(256) k_fc1(const float* __restrict__ w,
                                             const float* __restrict__ y2) {
    int ck = blockIdx.x;                  // K-chunk: m in [ck*16, ck*16+16)
    int t = threadIdx.x;                  // thread owns 2 j-cols, all 16 b
    __shared__ __align__(16) float xs[MPC * HID * 20];  // 41 KB, stride 20
    __shared__ float sc[32], sh[32];
    if (t < 32) { sc[t] = g_bn[t]; sh[t] = g_bn[32 + t]; }
    __syncthreads();
    {   // stage 16 rows: BN + ReLU + transpose to xs[kc*20 + b]
        int c0 = (t & 7) * 4;
        float s0 = sc[c0 + 0], s1 = sc[c0 + 1], s2 = sc[c0 + 2], s3 = sc[c0 + 3];
        float h0 = sh[c0 + 0], h1 = sh[c0 + 1], h2 = sh[c0 + 2], h3 = sh[c0 + 3];
#pragma unroll
        for (int p = 0; p < 8; p++) {
            int idx = t + p * 256;
            int mi = idx >> 7, q = idx & 127;
            int b = q >> 3;
            float4 v = *(const float4*)(y2 + ((size_t)(ck * MPC + mi)) * FW + q * 4);
            float* xr = xs + (mi * HID + c0) * 20;
            xr[b]          = fmaxf(s0 * v.x + h0, 0.f);
            xr[20 + b]     = fmaxf(s1 * v.y + h1, 0.f);
            xr[40 + b]     = fmaxf(s2 * v.z + h2, 0.f);
            xr[60 + b]     = fmaxf(s3 * v.w + h3, 0.f);
        }
    }
    __syncthreads();
    unsigned long long acc[16];           // [b-pair(8)][j(2)]
#pragma unroll
    for (int i = 0; i < 16; i++) acc[i] = 0ULL;
    int j0 = t * 2;
    const float* wp = w + (size_t)ck * (MPC * HID) * FW + j0;
    float2 cur = *(const float2*)(wp);
#pragma unroll 4
    for (int kc = 0; kc < MPC * HID; kc++) {
        float2 nxt = {0.f, 0.f};
        if (kc + 1 < MPC * HID) nxt = *(const float2*)(wp + (size_t)(kc + 1) * FW);
        unsigned long long w2x, w2y;
        PACKD(w2x, cur.x, cur.x);
        PACKD(w2y, cur.y, cur.y);
        const ulonglong2* xp = (const ulonglong2*)(xs + kc * 20);
#pragma unroll
        for (int q = 0; q < 4; q++) {
            ulonglong2 xv = xp[q];        // b-pairs (2q, 2q+1)
            FMA2(acc[(2 * q + 0) * 2 + 0], xv.x, w2x, acc[(2 * q + 0) * 2 + 0]);
            FMA2(acc[(2 * q + 0) * 2 + 1], xv.x, w2y, acc[(2 * q + 0) * 2 + 1]);
            FMA2(acc[(2 * q + 1) * 2 + 0], xv.y, w2x, acc[(2 * q + 1) * 2 + 0]);
            FMA2(acc[(2 * q + 1) * 2 + 1], xv.y, w2y, acc[(2 * q + 1) * 2 + 1]);
        }
        cur = nxt;
    }
    float* pbase = g_part + (size_t)ck * BSZ * FW + j0;
#pragma unroll
    for (int p = 0; p < 8; p++) {         // b-pair p -> rows 2p, 2p+1
        float lo0, hi0, lo1, hi1;
        UNPACKD(lo0, hi0, acc[p * 2 + 0]);
        UNPACKD(lo1, hi1, acc[p * 2 + 1]);
        float2 e = {lo0, lo1};
        float2 o = {hi0, hi1};
        *(float2*)(pbase + (size_t)(2 * p + 0) * FW) = e;
        *(float2*)(pbase + (size_t)(2 * p + 1) * FW) = o;
    }
}

// ================= reduce partials (stage 1, coalesced float4) ============
__global__ void k_red1() {
    int b = blockIdx.x >> 3;             // 0..15
    int grp = blockIdx.x & 7;            // 0..7, each covers 64 chunks
    int t = threadIdx.x;                 // 128 threads, j-quad each
    const float* p = g_part + (size_t)(grp * 64) * BSZ * FW + (size_t)b * FW + t * 4;
    float4 s = {0, 0, 0, 0};
#pragma unroll 8
    for (int k = 0; k < 64; k++) {
        float4 v = *(const float4*)(p + (size_t)k * BSZ * FW);
        s.x += v.x; s.y += v.y; s.z += v.z; s.w += v.w;
    }
    *(float4*)(g_red + (size_t)(b * 8 + grp) * FW + t * 4) = s;
}

// ================= final: reduce + extras + bias + relu + fc2 =============
__global__ void k_red2(const float* __restrict__ w, const float* __restrict__ fc1b,
                       const float* __restrict__ ex, const float* __restrict__ fc2w,
                       const float* __restrict__ fc2b, float* __restrict__ out) {
    int b = blockIdx.x;                  // 16 blocks
    int j = threadIdx.x;                 // 512 threads
    float acc = fc1b[j];
#pragma unroll
    for (int g = 0; g < 8; g++) acc += g_red[(size_t)(b * 8 + g) * FW + j];
#pragma unroll
    for (int e2 = 0; e2 < 32; e2++)
        acc += ex[b * 32 + e2] * w[((size_t)KTOT + e2) * FW + j];
    float h = fmaxf(acc, 0.f);
    __shared__ float r0[512], r1[512];
    r0[j] = h * fc2w[j * 2 + 0];
    r1[j] = h * fc2w[j * 2 + 1];
    __syncthreads();
    for (int s = 256; s > 0; s >>= 1) {
        if (j < s) { r0[j] += r0[j + s]; r1[j] += r1[j + s]; }
        __syncthreads();
    }
    if (j == 0) {
        out[b * 2 + 0] = r0[0] + fc2b[0];
        out[b * 2 + 1] = r1[0] + fc2b[1];
    }
}

// ================= launch ==================================================
extern "C" void kernel_launch(void* const* d_in, const int* in_sizes, int n_in,
                              void* d_out, int out_size) {
    const float* inputs  = (const float*)d_in[0];
    const float* ex      = (const float*)d_in[1];
    const int*   erow    = (const int*)  d_in[2];
    const int*   ecol    = (const int*)  d_in[3];
    const float* eval    = (const float*)d_in[4];
    const float* W1      = (const float*)d_in[5];
    const float* b1      = (const float*)d_in[6];
    const float* g1      = (const float*)d_in[7];
    const float* be1     = (const float*)d_in[8];
    const float* W2      = (const float*)d_in[9];
    const float* b2      = (const float*)d_in[10];
    const float* g2      = (const float*)d_in[11];
    const float* be2     = (const float*)d_in[12];
    const float* fc1w    = (const float*)d_in[13];
    const float* fc1b    = (const float*)d_in[14];
    const float* fc2w    = (const float*)d_in[15];
    const float* fc2b    = (const float*)d_in[16];
    float* out = (float*)d_out;

    float* bufA; cudaGetSymbolAddress((void**)&bufA, g_bufA);
    float* bufB; cudaGetSymbolAddress((void**)&bufB, g_bufB);
    int* cnt;    cudaGetSymbolAddress((void**)&cnt,  g_count);

    cudaMemsetAsync(cnt, 0, MM * sizeof(int));
    k_hist<<<NNZ / 1024, 256>>>(erow);
    k_scan<<<1, 1024>>>();
    k_scatter<<<NNZ / 1024, 256>>>(erow, ecol, eval);

    k_lin1<<<MM / 8, 256>>>(inputs, W1);                    // bufA = X@W1 (m,b,c)
    k_spmm<<<MM, 128>>>(bufA, b1, bufB);                    // bufB = L@bufA + b1, stats
    k_bn<<<64, 256>>>(g1, be1);
    k_lin2<<<(BSZ * MM) / 128, 256>>>(bufB, W2, bufA);      // bufA = bnrelu(bufB)@W2
    k_spmm<<<MM, 128>>>(bufA, b2, bufB);                    // bufB = L@bufA + b2, stats
    k_bn<<<64, 256>>>(g2, be2);

    k_fc1<<<NKCH, 256>>>(fc1w, bufB);                       // split-K partials
    k_red1<<<BSZ * 8, 128>>>();                             // coalesced partial reduce
    k_red2<<<BSZ, 512>>>(fc1w, fc1b, ex, fc2w, fc2b, out);  // finish + fc2
}